// round 7
// baseline (speedup 1.0000x reference)
#include <cuda_runtime.h>

#define BATCH   64
#define N       128
#define LAYERS  128
#define PAIRS   64
#define STEEP   10.0f
#define INV_PI  0.318309886183790671538f

// Scratch: alphas[batch][layer][pair]  (64*128*64 floats = 2MB)
__device__ float g_alphas[BATCH * LAYERS * PAIRS];

// ---------------------------------------------------------------------------
// Kernel A: one warp per batch. x held in registers: lane l owns x[4l..4l+3].
// Computes the serial 128-layer soft compare-exchange chain, emits all alphas
// to global scratch and the final x to d_out[0 .. 8191].
// ---------------------------------------------------------------------------
__global__ __launch_bounds__(32) void alpha_kernel(const float* __restrict__ in,
                                                   float* __restrict__ out_x) {
    const int b = blockIdx.x;
    const int l = threadIdx.x;  // lane 0..31

    const float4 xi = ((const float4*)(in + b * N))[l];
    float x0 = xi.x, x1 = xi.y, x2 = xi.z, x3 = xi.w;

    float2* aout = (float2*)(g_alphas + (size_t)b * LAYERS * PAIRS);

    #pragma unroll 2
    for (int L = 0; L < LAYERS; ++L) {
        float al0, al1;
        if ((L & 1) == 0) {
            // pairs (4l,4l+1)->p=2l  and  (4l+2,4l+3)->p=2l+1  (intra-lane)
            al0 = atanf(STEEP * (x1 - x0)) * INV_PI + 0.5f;
            al1 = atanf(STEEP * (x3 - x2)) * INV_PI + 0.5f;
            float n0 = al0 * x0 + (1.0f - al0) * x1;
            float n1 = (1.0f - al0) * x0 + al0 * x1;
            float n2 = al1 * x2 + (1.0f - al1) * x3;
            float n3 = (1.0f - al1) * x2 + al1 * x3;
            x0 = n0; x1 = n1; x2 = n2; x3 = n3;
        } else {
            // intra pair (4l+1,4l+2)->p=2l ; cross pair (4l+3, 4(l+1))->p=2l+1
            float bnext = __shfl_down_sync(0xffffffffu, x0, 1); // next lane's x0 (old)
            float pa    = __shfl_up_sync  (0xffffffffu, x3, 1); // prev lane's x3 (old)
            al0 = atanf(STEEP * (x2 - x1)) * INV_PI + 0.5f;
            al1 = atanf(STEEP * (bnext - x3)) * INV_PI + 0.5f;
            float alp = __shfl_up_sync(0xffffffffu, al1, 1);    // alpha of pair ending at my x0
            float n1 = al0 * x1 + (1.0f - al0) * x2;
            float n2 = (1.0f - al0) * x1 + al0 * x2;
            if (l < 31) x3 = al1 * x3 + (1.0f - al1) * bnext;
            if (l > 0)  x0 = (1.0f - alp) * pa + alp * x0;
            x1 = n1; x2 = n2;
        }
        aout[L * 32 + l] = make_float2(al0, al1);
    }

    ((float4*)(out_x + b * N))[l] = make_float4(x0, x1, x2, x3);
}

// ---------------------------------------------------------------------------
// Kernel B: permutation-matrix evolution. Each warp owns 4 rows of X of one
// batch, fully register-resident (lane l holds cols 4l..4l+3 of each row).
// Alphas preloaded to SMEM once; NO barriers inside the 128-layer loop.
// grid = BATCH*4 CTAs, 256 threads (8 warps -> 32 rows per CTA).
// ---------------------------------------------------------------------------
__global__ __launch_bounds__(256) void mix_kernel(float* __restrict__ out_X) {
    __shared__ float As[LAYERS * PAIRS];   // 32 KB

    const int b   = blockIdx.x >> 2;
    const int grp = blockIdx.x & 3;
    const int tid = threadIdx.x;

    // preload this batch's alphas (2048 float4 / 256 threads = 8 iters)
    {
        const float4* src = (const float4*)(g_alphas + (size_t)b * LAYERS * PAIRS);
        float4* dst = (float4*)As;
        #pragma unroll
        for (int i = 0; i < (LAYERS * PAIRS / 4) / 256; ++i)
            dst[tid + i * 256] = src[tid + i * 256];
    }
    __syncthreads();

    const int warp = tid >> 5;
    const int lane = tid & 31;
    const int row0 = grp * 32 + warp * 4;

    // X starts as identity
    float c[4][4];
    #pragma unroll
    for (int r = 0; r < 4; ++r)
        #pragma unroll
        for (int j = 0; j < 4; ++j)
            c[r][j] = ((row0 + r) == (4 * lane + j)) ? 1.0f : 0.0f;

    const float2* Af2 = (const float2*)As;

    for (int L = 0; L < LAYERS; ++L) {
        float2 a01 = Af2[L * 32 + lane];       // {alpha[2l], alpha[2l+1]}
        float a0 = a01.x, a1 = a01.y;
        if ((L & 1) == 0) {
            float b0 = 1.0f - a0, b1 = 1.0f - a1;
            #pragma unroll
            for (int r = 0; r < 4; ++r) {
                float A0 = c[r][0], B0 = c[r][1];
                c[r][0] = a0 * A0 + b0 * B0;
                c[r][1] = b0 * A0 + a0 * B0;
                float A1 = c[r][2], B1 = c[r][3];
                c[r][2] = a1 * A1 + b1 * B1;
                c[r][3] = b1 * A1 + a1 * B1;
            }
        } else {
            float ap = __shfl_up_sync(0xffffffffu, a1, 1);  // alpha[2l-1]
            float b0 = 1.0f - a0, b1 = 1.0f - a1, bp = 1.0f - ap;
            #pragma unroll
            for (int r = 0; r < 4; ++r) {
                float nb = __shfl_down_sync(0xffffffffu, c[r][0], 1); // next lane c0 (old)
                float pa = __shfl_up_sync  (0xffffffffu, c[r][3], 1); // prev lane c3 (old)
                float A0 = c[r][1], B0 = c[r][2];
                c[r][1] = a0 * A0 + b0 * B0;
                c[r][2] = b0 * A0 + a0 * B0;
                if (lane < 31) c[r][3] = a1 * c[r][3] + b1 * nb;
                if (lane > 0)  c[r][0] = bp * pa + ap * c[r][0];
            }
        }
    }

    float* outb = out_X + (size_t)b * N * N;
    #pragma unroll
    for (int r = 0; r < 4; ++r)
        ((float4*)(outb + (row0 + r) * N))[lane] =
            make_float4(c[r][0], c[r][1], c[r][2], c[r][3]);
}

extern "C" void kernel_launch(void* const* d_in, const int* in_sizes, int n_in,
                              void* d_out, int out_size) {
    (void)in_sizes; (void)n_in; (void)out_size;
    const float* vec = (const float*)d_in[0];
    float* out = (float*)d_out;

    // output layout: [x (64*128)] then [X (64*128*128)], matching (x, X) return
    alpha_kernel<<<BATCH, 32>>>(vec, out);
    mix_kernel<<<BATCH * 4, 256>>>(out + BATCH * N);
}

// round 8
// speedup vs baseline: 1.0130x; 1.0130x over previous
#include <cuda_runtime.h>

#define BATCH   64
#define N       128
#define LAYERS  128
#define PAIRS   64
#define STEEP   10.0f
#define INV_PI  0.318309886183790671538f

// Scratch: alphas[batch][layer][pair]  (64*128*64 floats = 2MB)
__device__ float g_alphas[BATCH * LAYERS * PAIRS];

// ---------------------------------------------------------------------------
// Kernel A: one warp per batch. x held in registers: lane l owns x[4l..4l+3].
// Computes the serial 128-layer soft compare-exchange chain, emits all alphas
// to global scratch and the final x to d_out[0 .. 8191].
// ---------------------------------------------------------------------------
__global__ __launch_bounds__(32) void alpha_kernel(const float* __restrict__ in,
                                                   float* __restrict__ out_x) {
    const int b = blockIdx.x;
    const int l = threadIdx.x;  // lane 0..31

    const float4 xi = ((const float4*)(in + b * N))[l];
    float x0 = xi.x, x1 = xi.y, x2 = xi.z, x3 = xi.w;

    float2* aout = (float2*)(g_alphas + (size_t)b * LAYERS * PAIRS);

    #pragma unroll 2
    for (int L = 0; L < LAYERS; ++L) {
        float al0, al1;
        if ((L & 1) == 0) {
            // pairs (4l,4l+1)->p=2l  and  (4l+2,4l+3)->p=2l+1  (intra-lane)
            al0 = atanf(STEEP * (x1 - x0)) * INV_PI + 0.5f;
            al1 = atanf(STEEP * (x3 - x2)) * INV_PI + 0.5f;
            float n0 = al0 * x0 + (1.0f - al0) * x1;
            float n1 = (1.0f - al0) * x0 + al0 * x1;
            float n2 = al1 * x2 + (1.0f - al1) * x3;
            float n3 = (1.0f - al1) * x2 + al1 * x3;
            x0 = n0; x1 = n1; x2 = n2; x3 = n3;
        } else {
            // intra pair (4l+1,4l+2)->p=2l ; cross pair (4l+3, 4(l+1))->p=2l+1
            float bnext = __shfl_down_sync(0xffffffffu, x0, 1); // next lane's x0 (old)
            float pa    = __shfl_up_sync  (0xffffffffu, x3, 1); // prev lane's x3 (old)
            al0 = atanf(STEEP * (x2 - x1)) * INV_PI + 0.5f;
            al1 = atanf(STEEP * (bnext - x3)) * INV_PI + 0.5f;
            float alp = __shfl_up_sync(0xffffffffu, al1, 1);    // alpha of pair ending at my x0
            float n1 = al0 * x1 + (1.0f - al0) * x2;
            float n2 = (1.0f - al0) * x1 + al0 * x2;
            if (l < 31) x3 = al1 * x3 + (1.0f - al1) * bnext;
            if (l > 0)  x0 = (1.0f - alp) * pa + alp * x0;
            x1 = n1; x2 = n2;
        }
        aout[L * 32 + l] = make_float2(al0, al1);
    }

    ((float4*)(out_x + b * N))[l] = make_float4(x0, x1, x2, x3);
}

// ---------------------------------------------------------------------------
// Kernel B: permutation-matrix evolution. Each warp owns 4 rows of X of one
// batch, fully register-resident (lane l holds cols 4l..4l+3 of each row).
// Alphas preloaded to SMEM once; NO barriers inside the 128-layer loop.
// grid = BATCH*4 CTAs, 256 threads (8 warps -> 32 rows per CTA).
// ---------------------------------------------------------------------------
__global__ __launch_bounds__(256) void mix_kernel(float* __restrict__ out_X) {
    __shared__ float As[LAYERS * PAIRS];   // 32 KB

    const int b   = blockIdx.x >> 2;
    const int grp = blockIdx.x & 3;
    const int tid = threadIdx.x;

    // preload this batch's alphas (2048 float4 / 256 threads = 8 iters)
    {
        const float4* src = (const float4*)(g_alphas + (size_t)b * LAYERS * PAIRS);
        float4* dst = (float4*)As;
        #pragma unroll
        for (int i = 0; i < (LAYERS * PAIRS / 4) / 256; ++i)
            dst[tid + i * 256] = src[tid + i * 256];
    }
    __syncthreads();

    const int warp = tid >> 5;
    const int lane = tid & 31;
    const int row0 = grp * 32 + warp * 4;

    // X starts as identity
    float c[4][4];
    #pragma unroll
    for (int r = 0; r < 4; ++r)
        #pragma unroll
        for (int j = 0; j < 4; ++j)
            c[r][j] = ((row0 + r) == (4 * lane + j)) ? 1.0f : 0.0f;

    const float2* Af2 = (const float2*)As;

    for (int L = 0; L < LAYERS; ++L) {
        float2 a01 = Af2[L * 32 + lane];       // {alpha[2l], alpha[2l+1]}
        float a0 = a01.x, a1 = a01.y;
        if ((L & 1) == 0) {
            float b0 = 1.0f - a0, b1 = 1.0f - a1;
            #pragma unroll
            for (int r = 0; r < 4; ++r) {
                float A0 = c[r][0], B0 = c[r][1];
                c[r][0] = a0 * A0 + b0 * B0;
                c[r][1] = b0 * A0 + a0 * B0;
                float A1 = c[r][2], B1 = c[r][3];
                c[r][2] = a1 * A1 + b1 * B1;
                c[r][3] = b1 * A1 + a1 * B1;
            }
        } else {
            float ap = __shfl_up_sync(0xffffffffu, a1, 1);  // alpha[2l-1]
            float b0 = 1.0f - a0, b1 = 1.0f - a1, bp = 1.0f - ap;
            #pragma unroll
            for (int r = 0; r < 4; ++r) {
                float nb = __shfl_down_sync(0xffffffffu, c[r][0], 1); // next lane c0 (old)
                float pa = __shfl_up_sync  (0xffffffffu, c[r][3], 1); // prev lane c3 (old)
                float A0 = c[r][1], B0 = c[r][2];
                c[r][1] = a0 * A0 + b0 * B0;
                c[r][2] = b0 * A0 + a0 * B0;
                if (lane < 31) c[r][3] = a1 * c[r][3] + b1 * nb;
                if (lane > 0)  c[r][0] = bp * pa + ap * c[r][0];
            }
        }
    }

    float* outb = out_X + (size_t)b * N * N;
    #pragma unroll
    for (int r = 0; r < 4; ++r)
        ((float4*)(outb + (row0 + r) * N))[lane] =
            make_float4(c[r][0], c[r][1], c[r][2], c[r][3]);
}

extern "C" void kernel_launch(void* const* d_in, const int* in_sizes, int n_in,
                              void* d_out, int out_size) {
    (void)in_sizes; (void)n_in; (void)out_size;
    const float* vec = (const float*)d_in[0];
    float* out = (float*)d_out;

    // output layout: [x (64*128)] then [X (64*128*128)], matching (x, X) return
    alpha_kernel<<<BATCH, 32>>>(vec, out);
    mix_kernel<<<BATCH * 4, 256>>>(out + BATCH * N);
}

// round 9
// speedup vs baseline: 1.6072x; 1.5865x over previous
#include <cuda_runtime.h>

#define BATCH   64
#define N       128
#define LAYERS  128
#define PAIRS   64
#define STEEP   10.0f
#define INV_PI  0.318309886183790671538f
#define FULL    0xffffffffu

// Scratch: alphas[batch][layer][pair]  (64*128*64 floats = 2MB)
__device__ float g_alphas[BATCH * LAYERS * PAIRS];

// ---------------------------------------------------------------------------
// Kernel A: one warp per batch. x in registers: lane l owns x[4l..4l+3].
// Serial 128-layer chain; branchless (edge lanes handled by zeroed blend
// coefficients, which make the cross-pair update an exact no-op).
// ---------------------------------------------------------------------------
__global__ __launch_bounds__(32) void alpha_kernel(const float* __restrict__ in,
                                                   float* __restrict__ out_x) {
    const int b = blockIdx.x;
    const int l = threadIdx.x;

    const float4 xi = ((const float4*)(in + b * N))[l];
    float x0 = xi.x, x1 = xi.y, x2 = xi.z, x3 = xi.w;

    float2* aout = (float2*)(g_alphas + (size_t)b * LAYERS * PAIRS);

    #pragma unroll 2
    for (int L = 0; L < LAYERS; L += 2) {
        // ---- even layer L: pairs (4l,4l+1) and (4l+2,4l+3), intra-lane ----
        {
            float d0 = x0 - x1;
            float d1 = x2 - x3;
            float al0 = atanf(STEEP * (x1 - x0)) * INV_PI + 0.5f;
            float al1 = atanf(STEEP * (x3 - x2)) * INV_PI + 0.5f;
            float n0 = fmaf(al0, d0, x1);   // al0*x0 + (1-al0)*x1
            float n1 = fmaf(-al0, d0, x0);  // (1-al0)*x0 + al0*x1
            float n2 = fmaf(al1, d1, x3);
            float n3 = fmaf(-al1, d1, x2);
            x0 = n0; x1 = n1; x2 = n2; x3 = n3;
            aout[L * 32 + l] = make_float2(al0, al1);
        }
        // ---- odd layer L+1: pair (4l+1,4l+2) intra; (4l+3, 4l+4) cross ----
        {
            float bn = __shfl_down_sync(FULL, x0, 1); // lane31 -> own x0 (unused)
            float pa = __shfl_up_sync  (FULL, x3, 1); // lane0  -> own x3 (unused)
            float dm = x1 - x2;
            float am = atanf(STEEP * (x2 - x1)) * INV_PI + 0.5f;
            float dc = bn - x3;
            float ac = atanf(STEEP * dc) * INV_PI + 0.5f;
            float alp = __shfl_up_sync(FULL, ac, 1);
            float b1z = (l == 31) ? 0.0f : (1.0f - ac);
            float bpz = (l == 0)  ? 0.0f : (1.0f - alp);
            float nx1 = fmaf(am, dm, x2);   // am*x1 + (1-am)*x2
            float nx2 = fmaf(-am, dm, x1);
            x3 = fmaf(b1z, dc, x3);         // ac*x3 + (1-ac)*bn ; no-op lane31
            x0 = fmaf(bpz, pa - x0, x0);    // (1-alp)*pa + alp*x0 ; no-op lane0
            x1 = nx1; x2 = nx2;
            aout[(L + 1) * 32 + l] = make_float2(am, ac);
        }
    }

    ((float4*)(out_x + b * N))[l] = make_float4(x0, x1, x2, x3);
}

// ---------------------------------------------------------------------------
// Kernel B: permutation-matrix evolution. Each warp owns 2 rows of X,
// register-resident (lane l holds cols 4l..4l+3 of each row). 4096 warps.
// No barriers or branches inside the layer loop.
// grid = BATCH*8 CTAs x 256 threads (8 warps -> 16 rows per CTA).
// ---------------------------------------------------------------------------
__global__ __launch_bounds__(256) void mix_kernel(float* __restrict__ out_X) {
    __shared__ float As[LAYERS * PAIRS];   // 32 KB

    const int b   = blockIdx.x >> 3;
    const int grp = blockIdx.x & 7;
    const int tid = threadIdx.x;

    {
        const float4* src = (const float4*)(g_alphas + (size_t)b * LAYERS * PAIRS);
        float4* dst = (float4*)As;
        #pragma unroll
        for (int i = 0; i < (LAYERS * PAIRS / 4) / 256; ++i)
            dst[tid + i * 256] = src[tid + i * 256];
    }
    __syncthreads();

    const int warp = tid >> 5;
    const int lane = tid & 31;
    const int row0 = grp * 16 + warp * 2;

    // X starts as identity
    float c[2][4];
    #pragma unroll
    for (int r = 0; r < 2; ++r)
        #pragma unroll
        for (int j = 0; j < 4; ++j)
            c[r][j] = ((row0 + r) == (4 * lane + j)) ? 1.0f : 0.0f;

    const float2* Af2 = (const float2*)As;

    #pragma unroll 2
    for (int L = 0; L < LAYERS; L += 2) {
        // ---- even layer ----
        float2 aE = Af2[L * 32 + lane];
        #pragma unroll
        for (int r = 0; r < 2; ++r) {
            float A0 = c[r][0], B0 = c[r][1], d0 = A0 - B0;
            c[r][0] = fmaf(aE.x, d0, B0);
            c[r][1] = fmaf(-aE.x, d0, A0);
            float A1 = c[r][2], B1 = c[r][3], d1 = A1 - B1;
            c[r][2] = fmaf(aE.y, d1, B1);
            c[r][3] = fmaf(-aE.y, d1, A1);
        }
        // ---- odd layer ----
        float2 aO = Af2[(L + 1) * 32 + lane];
        float ap  = __shfl_up_sync(FULL, aO.y, 1);
        float b1z = (lane == 31) ? 0.0f : (1.0f - aO.y);
        float bpz = (lane == 0)  ? 0.0f : (1.0f - ap);
        #pragma unroll
        for (int r = 0; r < 2; ++r) {
            float nb = __shfl_down_sync(FULL, c[r][0], 1); // next lane's c0
            float pa = __shfl_up_sync  (FULL, c[r][3], 1); // prev lane's c3
            float A = c[r][1], B = c[r][2], d = A - B;
            c[r][1] = fmaf(aO.x, d, B);
            c[r][2] = fmaf(-aO.x, d, A);
            c[r][3] = fmaf(b1z, nb - c[r][3], c[r][3]);    // no-op on lane31
            c[r][0] = fmaf(bpz, pa - c[r][0], c[r][0]);    // no-op on lane0
        }
    }

    float* outb = out_X + (size_t)b * N * N;
    #pragma unroll
    for (int r = 0; r < 2; ++r)
        ((float4*)(outb + (row0 + r) * N))[lane] =
            make_float4(c[r][0], c[r][1], c[r][2], c[r][3]);
}

extern "C" void kernel_launch(void* const* d_in, const int* in_sizes, int n_in,
                              void* d_out, int out_size) {
    (void)in_sizes; (void)n_in; (void)out_size;
    const float* vec = (const float*)d_in[0];
    float* out = (float*)d_out;

    // output layout: [x (64*128)] then [X (64*128*128)]
    alpha_kernel<<<BATCH, 32>>>(vec, out);
    mix_kernel<<<BATCH * 8, 256>>>(out + BATCH * N);
}